// round 11
// baseline (speedup 1.0000x reference)
#include <cuda_runtime.h>
#include <cstdint>

#define NNODES   50000
#define NEDGES   800000
#define DIM      64
#define NG       64
#define KIN      192
#define TE       128          // edges (or nodes) per block
#define AP       196          // A-tile pitch (K=192), mult of 4, ≡4 (mod 32)
#define TP       68           // 64-wide tile pitch, mult of 4, ≡4 (mod 32)
#define NP       132          // node A pitch (K=128)
#define RCUT     3.0f
#define NTHR     256

__device__ float g_msg[NNODES * DIM];

__device__ __forceinline__ float fsilu(float v)    { return v / (1.0f + __expf(-v)); }
__device__ __forceinline__ float fsigmoid(float v) { return 1.0f / (1.0f + __expf(-v)); }

__device__ __forceinline__ void red_add_v4(float* a, float x, float y, float z, float w) {
    asm volatile("red.global.add.v4.f32 [%0], {%1, %2, %3, %4};"
                 :: "l"(a), "f"(x), "f"(y), "f"(z), "f"(w) : "memory");
}
__device__ __forceinline__ void fma2(unsigned long long& d,
                                     unsigned long long a, unsigned long long b) {
    asm("fma.rn.f32x2 %0, %1, %2, %3;" : "=l"(d) : "l"(a), "l"(b), "l"(d));
}
// fold (even-k, odd-k) partial sums
__device__ __forceinline__ float fold1(unsigned long long v) {
    float lo, hi; asm("mov.b64 {%0, %1}, %2;" : "=f"(lo), "=f"(hi) : "l"(v));
    return lo + hi;
}

// ---------------------------------------------------------------------------
// K2 GEMM: thread tile 8 edges (stride 4) x 8 cols (stride 8), k-pair packed.
// A edge-major [e][k] pitch ap; W transposed [c][k] pitch wp. No packs.
// ---------------------------------------------------------------------------
__device__ __forceinline__ void gemm_k2(const float* __restrict__ Ab, int ap,
                                        const float* __restrict__ Wb, int wp,
                                        int kbeg, int kend, int e0, int cs,
                                        unsigned long long acc[8][8]) {
#pragma unroll
    for (int i = 0; i < 8; ++i)
#pragma unroll
        for (int j = 0; j < 8; ++j) acc[i][j] = 0ull;

#pragma unroll 2
    for (int k4 = kbeg; k4 < kend; k4 += 4) {
        ulonglong2 av[8], wv[8];
#pragma unroll
        for (int i = 0; i < 8; ++i)
            av[i] = *(const ulonglong2*)(Ab + (e0 + 4 * i) * ap + k4);
#pragma unroll
        for (int j = 0; j < 8; ++j)
            wv[j] = *(const ulonglong2*)(Wb + (cs + 8 * j) * wp + k4);
#pragma unroll
        for (int i = 0; i < 8; ++i)
#pragma unroll
            for (int j = 0; j < 8; ++j) {
                fma2(acc[i][j], av[i].x, wv[j].x);
                fma2(acc[i][j], av[i].y, wv[j].y);
            }
    }
}

// Combine k-split partials (group1 -> P, group0 adds + bias [+silu] -> T).
__device__ __forceinline__ void combine_store(unsigned long long acc[8][8],
                                              float* __restrict__ P,
                                              float* __restrict__ T,
                                              const float* __restrict__ bias,
                                              int g, int e0, int cs, bool do_silu) {
    if (g == 1) {
#pragma unroll
        for (int i = 0; i < 8; ++i)
#pragma unroll
            for (int j = 0; j < 8; ++j)
                P[(e0 + 4 * i) * TP + cs + 8 * j] = fold1(acc[i][j]);
    }
    __syncthreads();
    if (g == 0) {
        float b[8];
#pragma unroll
        for (int j = 0; j < 8; ++j) b[j] = bias[cs + 8 * j];
#pragma unroll
        for (int i = 0; i < 8; ++i)
#pragma unroll
            for (int j = 0; j < 8; ++j) {
                float v = fold1(acc[i][j]) + P[(e0 + 4 * i) * TP + cs + 8 * j] + b[j];
                T[(e0 + 4 * i) * TP + cs + 8 * j] = do_silu ? fsilu(v) : v;
            }
    }
    __syncthreads();
}

// ---------------------------------------------------------------------------
__global__ void init_kernel(const float* __restrict__ x, float* __restrict__ out) {
    const int tid = blockIdx.x * blockDim.x + threadIdx.x;
    const int stride = gridDim.x * blockDim.x;
    for (int i = tid; i < NNODES * DIM; i += stride) g_msg[i] = 0.0f;
    float* xo = out + (size_t)NNODES * DIM;
    for (int i = tid; i < NNODES * 3; i += stride) xo[i] = x[i];
}

// ---------------------------------------------------------------------------
// Edge kernel: 128 edges / block, 256 threads (8 warps, 2-way k-split GEMMs)
// ---------------------------------------------------------------------------
__global__ __launch_bounds__(NTHR, 1)
void edge_kernel(const float* __restrict__ h,   const float* __restrict__ x,
                 const int*   __restrict__ edst, const int*  __restrict__ esrc,
                 const float* __restrict__ means, const float* __restrict__ stds,
                 const float* __restrict__ Wm1, const float* __restrict__ bm1,
                 const float* __restrict__ Wm2, const float* __restrict__ bm2,
                 const float* __restrict__ Wa,  const float* __restrict__ ba,
                 const float* __restrict__ Wx1, const float* __restrict__ bx1,
                 const float* __restrict__ Wx2,
                 float* __restrict__ out) {
    extern __shared__ float sm[];
    float* Asm  = sm;                       // [128][196]; T1/U alias [0,8704), M [8704,17408)
    float* W1t  = Asm + 128 * AP;           // 64*196
    float* W2t  = W1t + 64 * AP;            // 64*68
    float* Wx1t = W2t + 64 * TP;            // 64*68
    float* P    = Wx1t + 64 * TP;           // 128*68
    float* bm1s = P + 128 * TP;             // 64
    float* bm2s = bm1s + 64;
    float* bx1s = bm2s + 64;
    float* Was  = bx1s + 64;
    float* Wx2s = Was + 64;
    float* bas  = Wx2s + 64;                // 1 (+3 pad)
    float* scale_s = bas + 4;               // 128
    float* mask_s  = scale_s + TE;          // 128
    float* dirx = mask_s + TE;
    float* diry = dirx + TE;
    float* dirz = diry + TE;
    int*   dst_s = (int*)(dirz + TE);       // 128

    const int tid  = threadIdx.x;
    const int wid  = tid >> 5;
    const int g    = wid >> 2;              // k-split group
    const int eb   = (wid & 3) * 32;        // warp edge block
    const int lane = tid & 31;
    const int er   = lane & 3;
    const int cs   = lane >> 2;
    const int e0   = eb + er;               // thread edges: e0 + 4i

    // ---- stage weights (transposed, k-contiguous rows) ----
    for (int idx = tid; idx < KIN * 64; idx += NTHR) {
        const int k = idx >> 6, c = idx & 63;
        W1t[c * AP + k] = Wm1[idx];
    }
    for (int idx = tid; idx < 64 * 64; idx += NTHR) {
        const int k = idx >> 6, c = idx & 63;
        W2t[c * TP + k]  = Wm2[idx];
        Wx1t[c * TP + k] = Wx1[idx];
    }
    if (tid < 64) {
        bm1s[tid] = bm1[tid];  bm2s[tid] = bm2[tid];  bx1s[tid] = bx1[tid];
        Was[tid]  = Wa[tid];   Wx2s[tid] = Wx2[tid];
    }
    if (tid == 0) bas[0] = ba[0];

    // ---- build A tile edge-major (2 threads per edge, straight copies) ----
    const int ebase = blockIdx.x * TE;
    {
        const int e = tid >> 1, half = tid & 1;
        const int ge = ebase + e;
        const int nd = edst[ge];
        const int ns = esrc[ge];
        const float dx = x[nd * 3 + 0] - x[ns * 3 + 0];
        const float dy = x[nd * 3 + 1] - x[ns * 3 + 1];
        const float dz = x[nd * 3 + 2] - x[ns * 3 + 2];
        const float dist = sqrtf(dx * dx + dy * dy + dz * dz);
        if (half == 0) {
            const float inv = 1.0f / dist;
            dirx[e] = dx * inv;  diry[e] = dy * inv;  dirz[e] = dz * inv;
            mask_s[e] = (dist <= RCUT) ? 1.0f : 0.0f;
            dst_s[e]  = nd;
        }
        const int f0 = half * 32;
        const float4* hd = (const float4*)(h + (size_t)nd * DIM + f0);
        const float4* hs = (const float4*)(h + (size_t)ns * DIM + f0);
        float4* Ad = (float4*)(Asm + e * AP + f0);
        float4* As = (float4*)(Asm + e * AP + 64 + f0);
#pragma unroll
        for (int i = 0; i < 8; ++i) Ad[i] = hd[i];
#pragma unroll
        for (int i = 0; i < 8; ++i) As[i] = hs[i];
#pragma unroll 8
        for (int i = 0; i < 32; ++i) {
            const int gg = f0 + i;
            const float t = (dist - __ldg(means + gg)) / __ldg(stds + gg);
            Asm[e * AP + 128 + gg] = __expf(-0.5f * t * t);
        }
    }
    __syncthreads();

    unsigned long long acc[8][8];
    float* T1 = Asm;                 // [128][68] aliases dead A rows
    float* M  = Asm + 128 * TP;      // next 8704 floats
    float* U  = Asm;                 // reuses T1 slot after layer2

    // ---- layer 1: [128,192] @ [192,64] ----
    gemm_k2(Asm, AP, W1t, AP, g * 96, g * 96 + 96, e0, cs, acc);
    combine_store(acc, P, T1, bm1s, g, e0, cs, true);

    // ---- layer 2: [128,64] @ [64,64] -> m ----
    gemm_k2(T1, TP, W2t, TP, g * 32, g * 32 + 32, e0, cs, acc);
    combine_store(acc, P, M, bm2s, g, e0, cs, true);

    // ---- attention (unscaled m) ----
    if (tid < TE) {
        float s = bas[0];
#pragma unroll
        for (int c4 = 0; c4 < 16; ++c4) {
            const float4 m4 = *(const float4*)(M + tid * TP + c4 * 4);
            const float4 w4 = *(const float4*)(Was + c4 * 4);
            s += m4.x * w4.x + m4.y * w4.y + m4.z * w4.z + m4.w * w4.w;
        }
        scale_s[tid] = fsigmoid(s) * mask_s[tid];
    }
    __syncthreads();

    // ---- scale m in place + scatter to g_msg (fused) ----
#pragma unroll
    for (int i = 0; i < (TE * 16) / NTHR; ++i) {
        const int q = tid + i * NTHR;
        const int e = q >> 4, c4 = (q & 15) * 4;
        float4 v = *(float4*)(M + e * TP + c4);
        const float sc = scale_s[e];
        v.x *= sc; v.y *= sc; v.z *= sc; v.w *= sc;
        *(float4*)(M + e * TP + c4) = v;
        red_add_v4(&g_msg[dst_s[e] * DIM + c4], v.x, v.y, v.z, v.w);
    }
    __syncthreads();

    // ---- x path: u = silu(m @ Wx1 + bx1) ----
    gemm_k2(M, TP, Wx1t, TP, g * 32, g * 32 + 32, e0, cs, acc);
    combine_store(acc, P, U, bx1s, g, e0, cs, true);

    // ---- disp magnitude + scatter into x_out ----
    if (tid < TE) {
        float s = 0.0f;
#pragma unroll
        for (int c4 = 0; c4 < 16; ++c4) {
            const float4 u4 = *(const float4*)(U + tid * TP + c4 * 4);
            const float4 w4 = *(const float4*)(Wx2s + c4 * 4);
            s += u4.x * w4.x + u4.y * w4.y + u4.z * w4.z + u4.w * w4.w;
        }
        const float w = tanhf(s) * mask_s[tid];
        float* xo = out + (size_t)NNODES * DIM + dst_s[tid] * 3;
        atomicAdd(xo + 0, dirx[tid] * w);
        atomicAdd(xo + 1, diry[tid] * w);
        atomicAdd(xo + 2, dirz[tid] * w);
    }
}

// ---------------------------------------------------------------------------
// Node kernel: h_out = h + silu([h | msg] @ Wh1 + bh1) @ Wh2 + bh2
// ---------------------------------------------------------------------------
__global__ __launch_bounds__(NTHR, 1)
void node_kernel(const float* __restrict__ h,
                 const float* __restrict__ Wh1, const float* __restrict__ bh1,
                 const float* __restrict__ Wh2, const float* __restrict__ bh2,
                 float* __restrict__ out) {
    extern __shared__ float sm[];
    float* Asm  = sm;                      // [128][132]; T1 alias [0,8704)
    float* Wh1t = Asm + 128 * NP;          // 64*132
    float* Wh2t = Wh1t + 64 * NP;          // 64*68
    float* P    = Wh2t + 64 * TP;          // 128*68
    float* T2   = P + 128 * TP;            // 128*68
    float* b1s  = T2 + 128 * TP;           // 64
    float* b2s  = b1s + 64;                // 64

    const int tid  = threadIdx.x;
    const int wid  = tid >> 5;
    const int g    = wid >> 2;
    const int eb   = (wid & 3) * 32;
    const int lane = tid & 31;
    const int er   = lane & 3;
    const int cs   = lane >> 2;
    const int e0   = eb + er;

    for (int idx = tid; idx < 128 * 64; idx += NTHR) {
        const int k = idx >> 6, c = idx & 63;
        Wh1t[c * NP + k] = Wh1[idx];
    }
    for (int idx = tid; idx < 64 * 64; idx += NTHR) {
        const int k = idx >> 6, c = idx & 63;
        Wh2t[c * TP + k] = Wh2[idx];
    }
    if (tid < 64) { b1s[tid] = bh1[tid]; b2s[tid] = bh2[tid]; }

    const int nbase = blockIdx.x * TE;
    {
        const int nl = tid >> 1, half = tid & 1;
        const int n = nbase + nl;
        const bool ok = (n < NNODES);
        const float4* src = half ? (const float4*)(g_msg + (size_t)n * DIM)
                                 : (const float4*)(h + (size_t)n * DIM);
        float4* dstp = (float4*)(Asm + nl * NP + half * 64);
#pragma unroll
        for (int i = 0; i < 16; ++i)
            dstp[i] = ok ? src[i] : make_float4(0.f, 0.f, 0.f, 0.f);
    }
    __syncthreads();

    unsigned long long acc[8][8];
    float* T1 = Asm;

    gemm_k2(Asm, NP, Wh1t, NP, g * 64, g * 64 + 64, e0, cs, acc);
    combine_store(acc, P, T1, b1s, g, e0, cs, true);

    gemm_k2(T1, TP, Wh2t, TP, g * 32, g * 32 + 32, e0, cs, acc);
    combine_store(acc, P, T2, b2s, g, e0, cs, false);

    // ---- residual add + coalesced write ----
#pragma unroll
    for (int i = 0; i < (TE * 16) / NTHR; ++i) {
        const int q = tid + i * NTHR;
        const int nl = q >> 4, c4 = (q & 15) * 4;
        const int n = nbase + nl;
        if (n < NNODES) {
            const float4 t = *(const float4*)(T2 + nl * TP + c4);
            const float4 hv = *(const float4*)(h + (size_t)n * DIM + c4);
            float4 o;
            o.x = t.x + hv.x;  o.y = t.y + hv.y;
            o.z = t.z + hv.z;  o.w = t.w + hv.w;
            *(float4*)(out + (size_t)n * DIM + c4) = o;
        }
    }
}

// ---------------------------------------------------------------------------
static const int EDGE_SMEM =
    (128 * AP + 64 * AP + 64 * TP + 64 * TP + 128 * TP
     + 64 * 5 + 4 + TE * 5 + TE) * (int)sizeof(float);
static const int NODE_SMEM =
    (128 * NP + 64 * NP + 64 * TP + 128 * TP + 128 * TP + 128) * (int)sizeof(float);

extern "C" void kernel_launch(void* const* d_in, const int* in_sizes, int n_in,
                              void* d_out, int out_size) {
    const float* h     = (const float*)d_in[0];
    const float* x     = (const float*)d_in[1];
    const int*   edst  = (const int*)  d_in[2];
    const int*   esrc  = (const int*)  d_in[3];
    const float* means = (const float*)d_in[4];
    const float* stds  = (const float*)d_in[5];
    const float* Wm1   = (const float*)d_in[6];
    const float* bm1   = (const float*)d_in[7];
    const float* Wm2   = (const float*)d_in[8];
    const float* bm2   = (const float*)d_in[9];
    const float* Wa    = (const float*)d_in[10];
    const float* ba    = (const float*)d_in[11];
    const float* Wx1   = (const float*)d_in[12];
    const float* bx1   = (const float*)d_in[13];
    const float* Wx2   = (const float*)d_in[14];
    const float* Wh1   = (const float*)d_in[15];
    const float* bh1   = (const float*)d_in[16];
    const float* Wh2   = (const float*)d_in[17];
    const float* bh2   = (const float*)d_in[18];
    float* out = (float*)d_out;

    cudaFuncSetAttribute(edge_kernel, cudaFuncAttributeMaxDynamicSharedMemorySize, EDGE_SMEM);
    cudaFuncSetAttribute(node_kernel, cudaFuncAttributeMaxDynamicSharedMemorySize, NODE_SMEM);

    init_kernel<<<592, 256>>>(x, out);
    edge_kernel<<<NEDGES / TE, NTHR, EDGE_SMEM>>>(
        h, x, edst, esrc, means, stds,
        Wm1, bm1, Wm2, bm2, Wa, ba, Wx1, bx1, Wx2, out);
    node_kernel<<<(NNODES + TE - 1) / TE, NTHR, NODE_SMEM>>>(
        h, Wh1, bh1, Wh2, bh2, out);
}

// round 13
// speedup vs baseline: 1.2367x; 1.2367x over previous
#include <cuda_runtime.h>
#include <cstdint>

#define NNODES   50000
#define NEDGES   800000
#define DIM      64
#define NG       64
#define KIN      192
#define TE       128          // edges (or nodes) per block
#define AP       196          // A pitch (K=192): %4==0, 4B*AP ≡ 16 (mod 128)
#define TP       68           // 64-K tile pitch: same property
#define NP       132          // node A pitch (K=128): same property
#define RCUT     3.0f
#define NTHR     256

__device__ float g_msg[NNODES * DIM];

__device__ __forceinline__ float fsilu(float v)    { return v / (1.0f + __expf(-v)); }
__device__ __forceinline__ float fsigmoid(float v) { return 1.0f / (1.0f + __expf(-v)); }

__device__ __forceinline__ void red_add_v4(float* a, float x, float y, float z, float w) {
    asm volatile("red.global.add.v4.f32 [%0], {%1, %2, %3, %4};"
                 :: "l"(a), "f"(x), "f"(y), "f"(z), "f"(w) : "memory");
}
__device__ __forceinline__ void fma2(unsigned long long& d,
                                     unsigned long long a, unsigned long long b) {
    asm("fma.rn.f32x2 %0, %1, %2, %3;" : "=l"(d) : "l"(a), "l"(b), "l"(d));
}
__device__ __forceinline__ float fold1(unsigned long long v) {
    float lo, hi; asm("mov.b64 {%0, %1}, %2;" : "=f"(lo), "=f"(hi) : "l"(v));
    return lo + hi;
}

// ---------------------------------------------------------------------------
// K-pair GEMM, tile 4 edges (stride 4) x 8 cols (stride 8) per thread.
// A edge-major [e][k] pitch ap; W transposed [c][k] pitch wp. Packed loads,
// zero pack MOVs. acc lanes hold (even-k, odd-k) partials; fold at store.
// ---------------------------------------------------------------------------
__device__ __forceinline__ void gemm4x8(const float* __restrict__ Ab, int ap,
                                        const float* __restrict__ Wb, int wp,
                                        int K, int e_base, int cs,
                                        unsigned long long acc[4][8]) {
#pragma unroll
    for (int i = 0; i < 4; ++i)
#pragma unroll
        for (int j = 0; j < 8; ++j) acc[i][j] = 0ull;

#pragma unroll 2
    for (int k4 = 0; k4 < K; k4 += 4) {
        ulonglong2 av[4], wv[8];
#pragma unroll
        for (int i = 0; i < 4; ++i)
            av[i] = *(const ulonglong2*)(Ab + (e_base + 4 * i) * ap + k4);
#pragma unroll
        for (int j = 0; j < 8; ++j)
            wv[j] = *(const ulonglong2*)(Wb + (cs + 8 * j) * wp + k4);
#pragma unroll
        for (int i = 0; i < 4; ++i)
#pragma unroll
            for (int j = 0; j < 8; ++j) {
                fma2(acc[i][j], av[i].x, wv[j].x);
                fma2(acc[i][j], av[i].y, wv[j].y);
            }
    }
}

// fold + bias (+silu) -> T[e][c] (pitch TP, k-contiguous for next layer)
__device__ __forceinline__ void store_act(float* __restrict__ T,
                                          unsigned long long acc[4][8],
                                          const float* __restrict__ bias,
                                          int e_base, int cs, bool do_silu) {
    float b[8];
#pragma unroll
    for (int j = 0; j < 8; ++j) b[j] = bias[cs + 8 * j];
#pragma unroll
    for (int i = 0; i < 4; ++i)
#pragma unroll
        for (int j = 0; j < 8; ++j) {
            const float v = fold1(acc[i][j]) + b[j];
            T[(e_base + 4 * i) * TP + cs + 8 * j] = do_silu ? fsilu(v) : v;
        }
}

// ---------------------------------------------------------------------------
__global__ void init_kernel(const float* __restrict__ x, float* __restrict__ out) {
    const int tid = blockIdx.x * blockDim.x + threadIdx.x;
    const int stride = gridDim.x * blockDim.x;
    for (int i = tid; i < NNODES * DIM; i += stride) g_msg[i] = 0.0f;
    float* xo = out + (size_t)NNODES * DIM;
    for (int i = tid; i < NNODES * 3; i += stride) xo[i] = x[i];
}

// ---------------------------------------------------------------------------
// Edge kernel: 128 edges / block, 256 threads (8 warps; warp = 16e x 64c)
// ---------------------------------------------------------------------------
__global__ __launch_bounds__(NTHR, 1)
void edge_kernel(const float* __restrict__ h,   const float* __restrict__ x,
                 const int*   __restrict__ edst, const int*  __restrict__ esrc,
                 const float* __restrict__ means, const float* __restrict__ stds,
                 const float* __restrict__ Wm1, const float* __restrict__ bm1,
                 const float* __restrict__ Wm2, const float* __restrict__ bm2,
                 const float* __restrict__ Wa,  const float* __restrict__ ba,
                 const float* __restrict__ Wx1, const float* __restrict__ bx1,
                 const float* __restrict__ Wx2,
                 float* __restrict__ out, int eoffset) {
    extern __shared__ float sm[];
    float* Asm  = sm;                       // [128][196]; T1/U alias [0,8704), M [8704,17408)
    float* W1t  = Asm + 128 * AP;           // 64 x AP
    float* W2t  = W1t + 64 * AP;            // 64 x TP
    float* Wx1t = W2t + 64 * TP;            // 64 x TP
    float* bm1s = Wx1t + 64 * TP;           // 64
    float* bm2s = bm1s + 64;
    float* bx1s = bm2s + 64;
    float* Was  = bx1s + 64;
    float* Wx2s = Was + 64;
    float* bas  = Wx2s + 64;                // 1 (+3 pad)
    float* scale_s = bas + 4;               // 128
    float* mask_s  = scale_s + TE;          // 128
    float* dirx = mask_s + TE;
    float* diry = dirx + TE;
    float* dirz = diry + TE;
    int*   dst_s = (int*)(dirz + TE);       // 128

    const int tid  = threadIdx.x;
    const int wid  = tid >> 5;
    const int lane = tid & 31;
    const int er   = lane & 3;
    const int cs   = lane >> 2;
    const int e_base = wid * 16 + er;       // thread edges: e_base + 4i, i<4

    // ---- stage weights transposed (k-contiguous rows) ----
    for (int idx = tid; idx < KIN * 64; idx += NTHR) {
        const int k = idx >> 6, c = idx & 63;
        W1t[c * AP + k] = Wm1[idx];
    }
    for (int idx = tid; idx < 64 * 64; idx += NTHR) {
        const int k = idx >> 6, c = idx & 63;
        W2t[c * TP + k]  = Wm2[idx];
        Wx1t[c * TP + k] = Wx1[idx];
    }
    if (tid < 64) {
        bm1s[tid] = bm1[tid];  bm2s[tid] = bm2[tid];  bx1s[tid] = bx1[tid];
        Was[tid]  = Wa[tid];   Wx2s[tid] = Wx2[tid];
    }
    if (tid == 0) bas[0] = ba[0];

    // ---- build A tile edge-major (2 threads per edge, straight copies) ----
    const int ebase = (blockIdx.x + eoffset) * TE;
    {
        const int e = tid >> 1, half = tid & 1;
        const int ge = ebase + e;
        const int nd = edst[ge];
        const int ns = esrc[ge];
        const float dx = x[nd * 3 + 0] - x[ns * 3 + 0];
        const float dy = x[nd * 3 + 1] - x[ns * 3 + 1];
        const float dz = x[nd * 3 + 2] - x[ns * 3 + 2];
        const float dist = sqrtf(dx * dx + dy * dy + dz * dz);
        if (half == 0) {
            const float inv = 1.0f / dist;
            dirx[e] = dx * inv;  diry[e] = dy * inv;  dirz[e] = dz * inv;
            mask_s[e] = (dist <= RCUT) ? 1.0f : 0.0f;
            dst_s[e]  = nd;
        }
        const int f0 = half * 32;
        const float4* hd = (const float4*)(h + (size_t)nd * DIM + f0);
        const float4* hs = (const float4*)(h + (size_t)ns * DIM + f0);
        float4* Ad = (float4*)(Asm + e * AP + f0);
        float4* As = (float4*)(Asm + e * AP + 64 + f0);
#pragma unroll
        for (int i = 0; i < 8; ++i) Ad[i] = hd[i];
#pragma unroll
        for (int i = 0; i < 8; ++i) As[i] = hs[i];
#pragma unroll 8
        for (int i = 0; i < 32; ++i) {
            const int gg = f0 + i;
            const float t = (dist - __ldg(means + gg)) / __ldg(stds + gg);
            Asm[e * AP + 128 + gg] = __expf(-0.5f * t * t);
        }
    }
    __syncthreads();

    unsigned long long acc[4][8];
    float* T1 = Asm;                 // [128][TP] aliases dead A rows
    float* M  = Asm + 128 * TP;
    float* U  = Asm;                 // reuses T1 slot after layer 2

    // ---- layer 1: [128,192] @ [192,64] ----
    gemm4x8(Asm, AP, W1t, AP, KIN, e_base, cs, acc);
    __syncthreads();                       // all A reads done before overwrite
    store_act(T1, acc, bm1s, e_base, cs, true);
    __syncthreads();

    // ---- layer 2: [128,64] @ [64,64] -> m ----
    gemm4x8(T1, TP, W2t, TP, 64, e_base, cs, acc);
    store_act(M, acc, bm2s, e_base, cs, true);   // M disjoint from T1
    __syncthreads();

    // ---- attention ----
    if (tid < TE) {
        float s = bas[0];
#pragma unroll
        for (int c4 = 0; c4 < 16; ++c4) {
            const float4 m4 = *(const float4*)(M + tid * TP + c4 * 4);
            const float4 w4 = *(const float4*)(Was + c4 * 4);
            s += m4.x * w4.x + m4.y * w4.y + m4.z * w4.z + m4.w * w4.w;
        }
        scale_s[tid] = fsigmoid(s) * mask_s[tid];
    }
    __syncthreads();

    // ---- scale m in place + scatter to g_msg (fused) ----
#pragma unroll
    for (int i = 0; i < (TE * 16) / NTHR; ++i) {
        const int q = tid + i * NTHR;
        const int e = q >> 4, c4 = (q & 15) * 4;
        float4 v = *(float4*)(M + e * TP + c4);
        const float sc = scale_s[e];
        v.x *= sc; v.y *= sc; v.z *= sc; v.w *= sc;
        *(float4*)(M + e * TP + c4) = v;
        red_add_v4(&g_msg[dst_s[e] * DIM + c4], v.x, v.y, v.z, v.w);
    }
    __syncthreads();

    // ---- x path: u = silu(m @ Wx1 + bx1) ----
    gemm4x8(M, TP, Wx1t, TP, 64, e_base, cs, acc);
    store_act(U, acc, bx1s, e_base, cs, true);   // U = T1 region, disjoint from M
    __syncthreads();

    // ---- disp magnitude + scatter into x_out ----
    if (tid < TE) {
        float s = 0.0f;
#pragma unroll
        for (int c4 = 0; c4 < 16; ++c4) {
            const float4 u4 = *(const float4*)(U + tid * TP + c4 * 4);
            const float4 w4 = *(const float4*)(Wx2s + c4 * 4);
            s += u4.x * w4.x + u4.y * w4.y + u4.z * w4.z + u4.w * w4.w;
        }
        const float w = tanhf(s) * mask_s[tid];
        float* xo = out + (size_t)NNODES * DIM + dst_s[tid] * 3;
        atomicAdd(xo + 0, dirx[tid] * w);
        atomicAdd(xo + 1, diry[tid] * w);
        atomicAdd(xo + 2, dirz[tid] * w);
    }
}

// ---------------------------------------------------------------------------
// Node kernel: h_out = h + silu([h | msg] @ Wh1 + bh1) @ Wh2 + bh2
// ---------------------------------------------------------------------------
__global__ __launch_bounds__(NTHR, 1)
void node_kernel(const float* __restrict__ h,
                 const float* __restrict__ Wh1, const float* __restrict__ bh1,
                 const float* __restrict__ Wh2, const float* __restrict__ bh2,
                 float* __restrict__ out) {
    extern __shared__ float sm[];
    float* Asm  = sm;                      // [128][NP]; T1 alias [0,8704)
    float* Wh1t = Asm + 128 * NP;          // 64 x NP
    float* Wh2t = Wh1t + 64 * NP;          // 64 x TP
    float* T2   = Wh2t + 64 * TP;          // 128 x TP
    float* b1s  = T2 + 128 * TP;           // 64
    float* b2s  = b1s + 64;                // 64

    const int tid  = threadIdx.x;
    const int wid  = tid >> 5;
    const int lane = tid & 31;
    const int er   = lane & 3;
    const int cs   = lane >> 2;
    const int e_base = wid * 16 + er;

    for (int idx = tid; idx < 128 * 64; idx += NTHR) {
        const int k = idx >> 6, c = idx & 63;
        Wh1t[c * NP + k] = Wh1[idx];
    }
    for (int idx = tid; idx < 64 * 64; idx += NTHR) {
        const int k = idx >> 6, c = idx & 63;
        Wh2t[c * TP + k] = Wh2[idx];
    }
    if (tid < 64) { b1s[tid] = bh1[tid]; b2s[tid] = bh2[tid]; }

    const int nbase = blockIdx.x * TE;
    {
        const int nl = tid >> 1, half = tid & 1;
        const int n = nbase + nl;
        const bool ok = (n < NNODES);
        const float4* src = half ? (const float4*)(g_msg + (size_t)n * DIM)
                                 : (const float4*)(h + (size_t)n * DIM);
        float4* dstp = (float4*)(Asm + nl * NP + half * 64);
#pragma unroll
        for (int i = 0; i < 16; ++i)
            dstp[i] = ok ? src[i] : make_float4(0.f, 0.f, 0.f, 0.f);
    }
    __syncthreads();

    unsigned long long acc[4][8];
    float* T1 = Asm;

    gemm4x8(Asm, NP, Wh1t, NP, 128, e_base, cs, acc);
    __syncthreads();
    store_act(T1, acc, b1s, e_base, cs, true);
    __syncthreads();

    gemm4x8(T1, TP, Wh2t, TP, 64, e_base, cs, acc);
    store_act(T2, acc, b2s, e_base, cs, false);
    __syncthreads();

    // ---- residual add + coalesced write ----
#pragma unroll
    for (int i = 0; i < (TE * 16) / NTHR; ++i) {
        const int q = tid + i * NTHR;
        const int nl = q >> 4, c4 = (q & 15) * 4;
        const int n = nbase + nl;
        if (n < NNODES) {
            const float4 t = *(const float4*)(T2 + nl * TP + c4);
            const float4 hv = *(const float4*)(h + (size_t)n * DIM + c4);
            float4 o;
            o.x = t.x + hv.x;  o.y = t.y + hv.y;
            o.z = t.z + hv.z;  o.w = t.w + hv.w;
            *(float4*)(out + (size_t)n * DIM + c4) = o;
        }
    }
}

// ---------------------------------------------------------------------------
static const int EDGE_SMEM =
    (128 * AP + 64 * AP + 64 * TP + 64 * TP
     + 64 * 5 + 4 + TE * 5 + TE) * (int)sizeof(float);
static const int NODE_SMEM =
    (128 * NP + 64 * NP + 64 * TP + 128 * TP + 128) * (int)sizeof(float);

extern "C" void kernel_launch(void* const* d_in, const int* in_sizes, int n_in,
                              void* d_out, int out_size) {
    const float* h     = (const float*)d_in[0];
    const float* x     = (const float*)d_in[1];
    const int*   edst  = (const int*)  d_in[2];
    const int*   esrc  = (const int*)  d_in[3];
    const float* means = (const float*)d_in[4];
    const float* stds  = (const float*)d_in[5];
    const float* Wm1   = (const float*)d_in[6];
    const float* bm1   = (const float*)d_in[7];
    const float* Wm2   = (const float*)d_in[8];
    const float* bm2   = (const float*)d_in[9];
    const float* Wa    = (const float*)d_in[10];
    const float* ba    = (const float*)d_in[11];
    const float* Wx1   = (const float*)d_in[12];
    const float* bx1   = (const float*)d_in[13];
    const float* Wx2   = (const float*)d_in[14];
    const float* Wh1   = (const float*)d_in[15];
    const float* bh1   = (const float*)d_in[16];
    const float* Wh2   = (const float*)d_in[17];
    const float* bh2   = (const float*)d_in[18];
    float* out = (float*)d_out;

    cudaFuncSetAttribute(edge_kernel, cudaFuncAttributeMaxDynamicSharedMemorySize, EDGE_SMEM);
    cudaFuncSetAttribute(node_kernel, cudaFuncAttributeMaxDynamicSharedMemorySize, NODE_SMEM);

    const int EBLOCKS = NEDGES / TE;       // 6250
    const int HALF    = EBLOCKS / 2;

    init_kernel<<<592, 256>>>(x, out);
    edge_kernel<<<HALF, NTHR, EDGE_SMEM>>>(
        h, x, edst, esrc, means, stds,
        Wm1, bm1, Wm2, bm2, Wa, ba, Wx1, bx1, Wx2, out, 0);
    edge_kernel<<<EBLOCKS - HALF, NTHR, EDGE_SMEM>>>(
        h, x, edst, esrc, means, stds,
        Wm1, bm1, Wm2, bm2, Wa, ba, Wx1, bx1, Wx2, out, HALF);
    node_kernel<<<(NNODES + TE - 1) / TE, NTHR, NODE_SMEM>>>(
        h, Wh1, bh1, Wh2, bh2, out);
}

// round 15
// speedup vs baseline: 1.3561x; 1.0966x over previous
#include <cuda_runtime.h>
#include <cstdint>

#define NNODES   50000
#define NEDGES   800000
#define DIM      64
#define NG       64
#define KIN      192
#define TE       128          // edges (or nodes) per block
#define AP       196          // A pitch (K=192): %4==0, 4B*AP ≡ 16 (mod 128)
#define TP       68           // 64-K tile pitch: same property
#define NP       132          // node A pitch (K=128): same property
#define RCUT     3.0f
#define NTHR     512

__device__ float g_msg[NNODES * DIM];

__device__ __forceinline__ float fsilu(float v)    { return v / (1.0f + __expf(-v)); }
__device__ __forceinline__ float fsigmoid(float v) { return 1.0f / (1.0f + __expf(-v)); }

__device__ __forceinline__ void red_add_v4(float* a, float x, float y, float z, float w) {
    asm volatile("red.global.add.v4.f32 [%0], {%1, %2, %3, %4};"
                 :: "l"(a), "f"(x), "f"(y), "f"(z), "f"(w) : "memory");
}
__device__ __forceinline__ void fma2(unsigned long long& d,
                                     unsigned long long a, unsigned long long b) {
    asm("fma.rn.f32x2 %0, %1, %2, %3;" : "=l"(d) : "l"(a), "l"(b), "l"(d));
}
__device__ __forceinline__ float fold1(unsigned long long v) {
    float lo, hi; asm("mov.b64 {%0, %1}, %2;" : "=f"(lo), "=f"(hi) : "l"(v));
    return lo + hi;
}

// ---------------------------------------------------------------------------
// K-pair GEMM, tile 2 edges (stride 4) x 8 cols (stride 8) per thread.
// A edge-major [e][k] pitch ap; W transposed [c][k] pitch wp. Packed loads,
// zero pack MOVs. acc lanes hold (even-k, odd-k) partials; fold at store.
// 512 threads: warp covers 8 edges x 64 cols; 16 warps cover 128 x 64.
// ---------------------------------------------------------------------------
__device__ __forceinline__ void gemm2x8(const float* __restrict__ Ab, int ap,
                                        const float* __restrict__ Wb, int wp,
                                        int K, int e_base, int cs,
                                        unsigned long long acc[2][8]) {
#pragma unroll
    for (int i = 0; i < 2; ++i)
#pragma unroll
        for (int j = 0; j < 8; ++j) acc[i][j] = 0ull;

#pragma unroll 2
    for (int k4 = 0; k4 < K; k4 += 4) {
        ulonglong2 av[2], wv[8];
#pragma unroll
        for (int i = 0; i < 2; ++i)
            av[i] = *(const ulonglong2*)(Ab + (e_base + 4 * i) * ap + k4);
#pragma unroll
        for (int j = 0; j < 8; ++j)
            wv[j] = *(const ulonglong2*)(Wb + (cs + 8 * j) * wp + k4);
#pragma unroll
        for (int i = 0; i < 2; ++i)
#pragma unroll
            for (int j = 0; j < 8; ++j) {
                fma2(acc[i][j], av[i].x, wv[j].x);
                fma2(acc[i][j], av[i].y, wv[j].y);
            }
    }
}

// fold + bias (+silu) -> T[e][c] (pitch TP, k-contiguous for next layer)
__device__ __forceinline__ void store_act(float* __restrict__ T,
                                          unsigned long long acc[2][8],
                                          const float* __restrict__ bias,
                                          int e_base, int cs, bool do_silu) {
    float b[8];
#pragma unroll
    for (int j = 0; j < 8; ++j) b[j] = bias[cs + 8 * j];
#pragma unroll
    for (int i = 0; i < 2; ++i)
#pragma unroll
        for (int j = 0; j < 8; ++j) {
            const float v = fold1(acc[i][j]) + b[j];
            T[(e_base + 4 * i) * TP + cs + 8 * j] = do_silu ? fsilu(v) : v;
        }
}

// ---------------------------------------------------------------------------
__global__ void init_kernel(const float* __restrict__ x, float* __restrict__ out) {
    const int tid = blockIdx.x * blockDim.x + threadIdx.x;
    const int stride = gridDim.x * blockDim.x;
    for (int i = tid; i < NNODES * DIM; i += stride) g_msg[i] = 0.0f;
    float* xo = out + (size_t)NNODES * DIM;
    for (int i = tid; i < NNODES * 3; i += stride) xo[i] = x[i];
}

// ---------------------------------------------------------------------------
// Edge kernel: 128 edges / block, 512 threads (16 warps -> 4/SMSP)
// ---------------------------------------------------------------------------
__global__ __launch_bounds__(NTHR, 1)
void edge_kernel(const float* __restrict__ h,   const float* __restrict__ x,
                 const int*   __restrict__ edst, const int*  __restrict__ esrc,
                 const float* __restrict__ means, const float* __restrict__ stds,
                 const float* __restrict__ Wm1, const float* __restrict__ bm1,
                 const float* __restrict__ Wm2, const float* __restrict__ bm2,
                 const float* __restrict__ Wa,  const float* __restrict__ ba,
                 const float* __restrict__ Wx1, const float* __restrict__ bx1,
                 const float* __restrict__ Wx2,
                 float* __restrict__ out, int eoffset) {
    extern __shared__ float sm[];
    float* Asm  = sm;                       // [128][196]; T1/U alias [0,8704), M [8704,17408)
    float* W1t  = Asm + 128 * AP;           // 64 x AP
    float* W2t  = W1t + 64 * AP;            // 64 x TP
    float* Wx1t = W2t + 64 * TP;            // 64 x TP
    float* bm1s = Wx1t + 64 * TP;           // 64
    float* bm2s = bm1s + 64;
    float* bx1s = bm2s + 64;
    float* Was  = bx1s + 64;
    float* Wx2s = Was + 64;
    float* bas  = Wx2s + 64;                // 1 (+3 pad)
    float* scale_s = bas + 4;               // 128
    float* mask_s  = scale_s + TE;          // 128
    float* dirx = mask_s + TE;
    float* diry = dirx + TE;
    float* dirz = diry + TE;
    int*   dst_s = (int*)(dirz + TE);       // 128

    const int tid  = threadIdx.x;
    const int wid  = tid >> 5;
    const int lane = tid & 31;
    const int er   = lane & 3;
    const int cs   = lane >> 2;
    const int e_base = wid * 8 + er;        // thread edges: e_base, e_base+4

    // ---- stage weights transposed (k-contiguous rows) ----
    for (int idx = tid; idx < KIN * 64; idx += NTHR) {
        const int k = idx >> 6, c = idx & 63;
        W1t[c * AP + k] = Wm1[idx];
    }
    for (int idx = tid; idx < 64 * 64; idx += NTHR) {
        const int k = idx >> 6, c = idx & 63;
        W2t[c * TP + k]  = Wm2[idx];
        Wx1t[c * TP + k] = Wx1[idx];
    }
    if (tid < 64) {
        bm1s[tid] = bm1[tid];  bm2s[tid] = bm2[tid];  bx1s[tid] = bx1[tid];
        Was[tid]  = Wa[tid];   Wx2s[tid] = Wx2[tid];
    }
    if (tid == 0) bas[0] = ba[0];

    // ---- build A tile edge-major (4 threads per edge, 16 features each) ----
    const int ebase = (blockIdx.x + eoffset) * TE;
    {
        const int e = tid >> 2, q = tid & 3;
        const int ge = ebase + e;
        const int nd = edst[ge];
        const int ns = esrc[ge];
        const float dx = x[nd * 3 + 0] - x[ns * 3 + 0];
        const float dy = x[nd * 3 + 1] - x[ns * 3 + 1];
        const float dz = x[nd * 3 + 2] - x[ns * 3 + 2];
        const float dist = sqrtf(dx * dx + dy * dy + dz * dz);
        if (q == 0) {
            const float inv = 1.0f / dist;
            dirx[e] = dx * inv;  diry[e] = dy * inv;  dirz[e] = dz * inv;
            mask_s[e] = (dist <= RCUT) ? 1.0f : 0.0f;
            dst_s[e]  = nd;
        }
        const int f0 = q * 16;
        const float4* hd = (const float4*)(h + (size_t)nd * DIM + f0);
        const float4* hs = (const float4*)(h + (size_t)ns * DIM + f0);
        float4* Ad = (float4*)(Asm + e * AP + f0);
        float4* As = (float4*)(Asm + e * AP + 64 + f0);
#pragma unroll
        for (int i = 0; i < 4; ++i) Ad[i] = hd[i];
#pragma unroll
        for (int i = 0; i < 4; ++i) As[i] = hs[i];
#pragma unroll 8
        for (int i = 0; i < 16; ++i) {
            const int gg = f0 + i;
            const float t = (dist - __ldg(means + gg)) / __ldg(stds + gg);
            Asm[e * AP + 128 + gg] = __expf(-0.5f * t * t);
        }
    }
    __syncthreads();

    unsigned long long acc[2][8];
    float* T1 = Asm;                 // [128][TP] aliases dead A rows
    float* M  = Asm + 128 * TP;
    float* U  = Asm;                 // reuses T1 slot after layer 2

    // ---- layer 1: [128,192] @ [192,64] ----
    gemm2x8(Asm, AP, W1t, AP, KIN, e_base, cs, acc);
    __syncthreads();                       // all A reads done before overwrite
    store_act(T1, acc, bm1s, e_base, cs, true);
    __syncthreads();

    // ---- layer 2: [128,64] @ [64,64] -> m ----
    gemm2x8(T1, TP, W2t, TP, 64, e_base, cs, acc);
    store_act(M, acc, bm2s, e_base, cs, true);   // M disjoint from T1
    __syncthreads();

    // ---- attention ----
    if (tid < TE) {
        float s = bas[0];
#pragma unroll
        for (int c4 = 0; c4 < 16; ++c4) {
            const float4 m4 = *(const float4*)(M + tid * TP + c4 * 4);
            const float4 w4 = *(const float4*)(Was + c4 * 4);
            s += m4.x * w4.x + m4.y * w4.y + m4.z * w4.z + m4.w * w4.w;
        }
        scale_s[tid] = fsigmoid(s) * mask_s[tid];
    }
    __syncthreads();

    // ---- scale m in place + scatter to g_msg (fused) ----
#pragma unroll
    for (int i = 0; i < (TE * 16) / NTHR; ++i) {
        const int q = tid + i * NTHR;
        const int e = q >> 4, c4 = (q & 15) * 4;
        float4 v = *(float4*)(M + e * TP + c4);
        const float sc = scale_s[e];
        v.x *= sc; v.y *= sc; v.z *= sc; v.w *= sc;
        *(float4*)(M + e * TP + c4) = v;
        red_add_v4(&g_msg[dst_s[e] * DIM + c4], v.x, v.y, v.z, v.w);
    }
    __syncthreads();

    // ---- x path: u = silu(m @ Wx1 + bx1) ----
    gemm2x8(M, TP, Wx1t, TP, 64, e_base, cs, acc);
    store_act(U, acc, bx1s, e_base, cs, true);   // U = T1 region, disjoint from M
    __syncthreads();

    // ---- disp magnitude + scatter into x_out ----
    if (tid < TE) {
        float s = 0.0f;
#pragma unroll
        for (int c4 = 0; c4 < 16; ++c4) {
            const float4 u4 = *(const float4*)(U + tid * TP + c4 * 4);
            const float4 w4 = *(const float4*)(Wx2s + c4 * 4);
            s += u4.x * w4.x + u4.y * w4.y + u4.z * w4.z + u4.w * w4.w;
        }
        const float w = tanhf(s) * mask_s[tid];
        float* xo = out + (size_t)NNODES * DIM + dst_s[tid] * 3;
        atomicAdd(xo + 0, dirx[tid] * w);
        atomicAdd(xo + 1, diry[tid] * w);
        atomicAdd(xo + 2, dirz[tid] * w);
    }
}

// ---------------------------------------------------------------------------
// Node kernel: h_out = h + silu([h | msg] @ Wh1 + bh1) @ Wh2 + bh2
// ---------------------------------------------------------------------------
__global__ __launch_bounds__(NTHR, 1)
void node_kernel(const float* __restrict__ h,
                 const float* __restrict__ Wh1, const float* __restrict__ bh1,
                 const float* __restrict__ Wh2, const float* __restrict__ bh2,
                 float* __restrict__ out) {
    extern __shared__ float sm[];
    float* Asm  = sm;                      // [128][NP]; T1 alias [0,8704)
    float* Wh1t = Asm + 128 * NP;          // 64 x NP
    float* Wh2t = Wh1t + 64 * NP;          // 64 x TP
    float* T2   = Wh2t + 64 * TP;          // 128 x TP
    float* b1s  = T2 + 128 * TP;           // 64
    float* b2s  = b1s + 64;                // 64

    const int tid  = threadIdx.x;
    const int wid  = tid >> 5;
    const int lane = tid & 31;
    const int er   = lane & 3;
    const int cs   = lane >> 2;
    const int e_base = wid * 8 + er;

    for (int idx = tid; idx < 128 * 64; idx += NTHR) {
        const int k = idx >> 6, c = idx & 63;
        Wh1t[c * NP + k] = Wh1[idx];
    }
    for (int idx = tid; idx < 64 * 64; idx += NTHR) {
        const int k = idx >> 6, c = idx & 63;
        Wh2t[c * TP + k] = Wh2[idx];
    }
    if (tid < 64) { b1s[tid] = bh1[tid]; b2s[tid] = bh2[tid]; }

    const int nbase = blockIdx.x * TE;
    {
        const int nl = tid >> 2, q = tid & 3;
        const int n = nbase + nl;
        const bool ok = (n < NNODES);
        const float* srcp = (q < 2) ? (h + (size_t)n * DIM + q * 32)
                                    : (g_msg + (size_t)n * DIM + (q - 2) * 32);
        float4* dstp = (float4*)(Asm + nl * NP + q * 32);
#pragma unroll
        for (int i = 0; i < 8; ++i)
            dstp[i] = ok ? ((const float4*)srcp)[i] : make_float4(0.f, 0.f, 0.f, 0.f);
    }
    __syncthreads();

    unsigned long long acc[2][8];
    float* T1 = Asm;

    gemm2x8(Asm, NP, Wh1t, NP, 128, e_base, cs, acc);
    __syncthreads();
    store_act(T1, acc, b1s, e_base, cs, true);
    __syncthreads();

    gemm2x8(T1, TP, Wh2t, TP, 64, e_base, cs, acc);
    store_act(T2, acc, b2s, e_base, cs, false);
    __syncthreads();

    // ---- residual add + coalesced write ----
#pragma unroll
    for (int i = 0; i < (TE * 16) / NTHR; ++i) {
        const int q = tid + i * NTHR;
        const int nl = q >> 4, c4 = (q & 15) * 4;
        const int n = nbase + nl;
        if (n < NNODES) {
            const float4 t = *(const float4*)(T2 + nl * TP + c4);
            const float4 hv = *(const float4*)(h + (size_t)n * DIM + c4);
            float4 o;
            o.x = t.x + hv.x;  o.y = t.y + hv.y;
            o.z = t.z + hv.z;  o.w = t.w + hv.w;
            *(float4*)(out + (size_t)n * DIM + c4) = o;
        }
    }
}

// ---------------------------------------------------------------------------
static const int EDGE_SMEM =
    (128 * AP + 64 * AP + 64 * TP + 64 * TP
     + 64 * 5 + 4 + TE * 5 + TE) * (int)sizeof(float);
static const int NODE_SMEM =
    (128 * NP + 64 * NP + 64 * TP + 128 * TP + 128) * (int)sizeof(float);

extern "C" void kernel_launch(void* const* d_in, const int* in_sizes, int n_in,
                              void* d_out, int out_size) {
    const float* h     = (const float*)d_in[0];
    const float* x     = (const float*)d_in[1];
    const int*   edst  = (const int*)  d_in[2];
    const int*   esrc  = (const int*)  d_in[3];
    const float* means = (const float*)d_in[4];
    const float* stds  = (const float*)d_in[5];
    const float* Wm1   = (const float*)d_in[6];
    const float* bm1   = (const float*)d_in[7];
    const float* Wm2   = (const float*)d_in[8];
    const float* bm2   = (const float*)d_in[9];
    const float* Wa    = (const float*)d_in[10];
    const float* ba    = (const float*)d_in[11];
    const float* Wx1   = (const float*)d_in[12];
    const float* bx1   = (const float*)d_in[13];
    const float* Wx2   = (const float*)d_in[14];
    const float* Wh1   = (const float*)d_in[15];
    const float* bh1   = (const float*)d_in[16];
    const float* Wh2   = (const float*)d_in[17];
    const float* bh2   = (const float*)d_in[18];
    float* out = (float*)d_out;

    cudaFuncSetAttribute(edge_kernel, cudaFuncAttributeMaxDynamicSharedMemorySize, EDGE_SMEM);
    cudaFuncSetAttribute(node_kernel, cudaFuncAttributeMaxDynamicSharedMemorySize, NODE_SMEM);

    const int EBLOCKS = NEDGES / TE;       // 6250
    const int HALF    = EBLOCKS / 2;

    init_kernel<<<592, 256>>>(x, out);
    edge_kernel<<<HALF, NTHR, EDGE_SMEM>>>(
        h, x, edst, esrc, means, stds,
        Wm1, bm1, Wm2, bm2, Wa, ba, Wx1, bx1, Wx2, out, 0);
    edge_kernel<<<EBLOCKS - HALF, NTHR, EDGE_SMEM>>>(
        h, x, edst, esrc, means, stds,
        Wm1, bm1, Wm2, bm2, Wa, ba, Wx1, bx1, Wx2, out, HALF);
    node_kernel<<<(NNODES + TE - 1) / TE, NTHR, NODE_SMEM>>>(
        h, Wh1, bh1, Wh2, bh2, out);
}